// round 1
// baseline (speedup 1.0000x reference)
#include <cuda_runtime.h>
#include <cuda_bf16.h>
#include <math.h>

// Problem constants (from reference_code)
#define PB  32      // batch / episodes
#define PS  50      // n_support
#define PQ  75      // n_query
#define PT  128     // time steps
#define PF  64      // features
#define PD  256     // embedding dim
#define PK  5       // N_WAY

#define N_SUP_SAMPLES (PB * PS)          // 1600
#define N_QRY_SAMPLES (PB * PQ)          // 2400
#define N_SAMPLES     (N_SUP_SAMPLES + N_QRY_SAMPLES)  // 4000

// Scratch (device globals — no allocation allowed)
__device__ float g_xm[N_SAMPLES * PF];        // time-mean per sample [4000, 64]
__device__ float g_pxm[PB * PK * PF];         // per-episode class-mean of xm [32,5,64]

// ---------------------------------------------------------------------------
// Kernel 1: time-mean pooling.  One block per sample, 256 threads.
// Sample layout: [T=128, F=64] contiguous floats = 2048 float4.
// Thread tid loads float4 index j = tid + 256*i (i=0..7).  Since 256%16==0,
// j%16 == tid%16 is constant per thread, so each thread's float4 always
// covers the same 4 features f = 4*(tid%16) .. +3.
// ---------------------------------------------------------------------------
__global__ __launch_bounds__(256) void meanpool_kernel(
    const float* __restrict__ support_x,
    const float* __restrict__ query_x,
    float* __restrict__ xm)
{
    const int bid = blockIdx.x;            // 0..3999
    const int tid = threadIdx.x;

    const float* src;
    if (bid < N_SUP_SAMPLES) src = support_x + (size_t)bid * (PT * PF);
    else                     src = query_x   + (size_t)(bid - N_SUP_SAMPLES) * (PT * PF);

    const float4* src4 = reinterpret_cast<const float4*>(src);

    float4 acc = make_float4(0.f, 0.f, 0.f, 0.f);
#pragma unroll
    for (int i = 0; i < 8; i++) {
        float4 v = src4[tid + 256 * i];
        acc.x += v.x; acc.y += v.y; acc.z += v.z; acc.w += v.w;
    }

    __shared__ float sm[256 * 4];
    sm[tid * 4 + 0] = acc.x;
    sm[tid * 4 + 1] = acc.y;
    sm[tid * 4 + 2] = acc.z;
    sm[tid * 4 + 3] = acc.w;
    __syncthreads();

    if (tid < PF) {
        const int c = tid >> 2;     // which 4-feature group (0..15)
        const int k = tid & 3;      // component within float4
        float s = 0.f;
#pragma unroll
        for (int r = 0; r < 16; r++)
            s += sm[(c + 16 * r) * 4 + k];
        xm[(size_t)bid * PF + tid] = s * (1.0f / (float)PT);
    }
}

// ---------------------------------------------------------------------------
// Kernel 2: prototype feature means per episode.
// 32 blocks (one per episode), 64 threads (one per feature f).
// acc[k] is a static 5-entry register array; dynamic class index handled
// with predicated adds (no local-memory spill).
// ---------------------------------------------------------------------------
__global__ __launch_bounds__(64) void proto_kernel(
    const int* __restrict__ support_y,
    const float* __restrict__ xm,
    float* __restrict__ pxm)
{
    const int b = blockIdx.x;
    const int f = threadIdx.x;

    __shared__ int ys[PS];
    if (f < PS) ys[f] = support_y[b * PS + f];
    __syncthreads();

    float acc[PK];
    float cnt[PK];
#pragma unroll
    for (int k = 0; k < PK; k++) { acc[k] = 0.f; cnt[k] = 0.f; }

    for (int s = 0; s < PS; s++) {
        const int y = ys[s];
        const float v = xm[(size_t)(b * PS + s) * PF + f];
#pragma unroll
        for (int k = 0; k < PK; k++) {
            const bool hit = (y == k);
            acc[k] += hit ? v : 0.f;
            cnt[k] += hit ? 1.f : 0.f;
        }
    }
#pragma unroll
    for (int k = 0; k < PK; k++) {
        const float c = (cnt[k] > 0.f) ? cnt[k] : 1.f;
        pxm[((size_t)b * PK + k) * PF + f] = acc[k] / c;
    }
}

// ---------------------------------------------------------------------------
// Kernel 3: logits.  Grid = 32 episodes * 5 query-chunks = 160 blocks,
// 256 threads; thread tid owns output dim d = tid.
// Bias b cancels in (query_z - proto_z), so it is never needed.
// Each thread keeps its W column (64 floats) in registers.
// ---------------------------------------------------------------------------
#define QCHUNK 15   // queries per block (75 / 5)

__global__ __launch_bounds__(256) void logits_kernel(
    const float* __restrict__ xm,     // g_xm
    const float* __restrict__ pxm,    // g_pxm
    const float* __restrict__ W,      // [F, D] row-major (f*256 + d)
    float* __restrict__ out)          // [B*Q, K]
{
    const int b  = blockIdx.x / (PQ / QCHUNK);   // episode
    const int qc = blockIdx.x % (PQ / QCHUNK);   // query chunk
    const int d  = threadIdx.x;                  // output dim
    const int tid = threadIdx.x;

    // W column in registers (coalesced loads across threads)
    float Wc[PF];
#pragma unroll
    for (int f = 0; f < PF; f++)
        Wc[f] = W[f * PD + d];

    __shared__ float s_pxm[PK * PF];        // 5*64
    __shared__ float s_qxm[QCHUNK * PF];    // 15*64
    __shared__ float s_red[8][PK];          // per-warp partial distances

    for (int i = tid; i < PK * PF; i += 256)
        s_pxm[i] = pxm[(size_t)b * PK * PF + i];
    {
        const float* qbase = xm + (size_t)(N_SUP_SAMPLES + b * PQ + qc * QCHUNK) * PF;
        for (int i = tid; i < QCHUNK * PF; i += 256)
            s_qxm[i] = qbase[i];
    }
    __syncthreads();

    // prototype projections for this thread's dim (bias cancels)
    float pz[PK];
#pragma unroll
    for (int k = 0; k < PK; k++) {
        float s = 0.f;
#pragma unroll
        for (int f = 0; f < PF; f++)
            s += s_pxm[k * PF + f] * Wc[f];
        pz[k] = s;
    }

    const int warp = tid >> 5;
    const int lane = tid & 31;

    for (int q = 0; q < QCHUNK; q++) {
        float zq = 0.f;
#pragma unroll
        for (int f = 0; f < PF; f++)
            zq += s_qxm[q * PF + f] * Wc[f];

        float d2[PK];
#pragma unroll
        for (int k = 0; k < PK; k++) {
            const float df = zq - pz[k];
            d2[k] = df * df;
        }
        // butterfly reduce over warp
#pragma unroll
        for (int off = 16; off > 0; off >>= 1) {
#pragma unroll
            for (int k = 0; k < PK; k++)
                d2[k] += __shfl_xor_sync(0xFFFFFFFFu, d2[k], off);
        }
        if (lane == 0) {
#pragma unroll
            for (int k = 0; k < PK; k++)
                s_red[warp][k] = d2[k];
        }
        __syncthreads();
        if (tid < PK) {
            float s = 0.f;
#pragma unroll
            for (int w = 0; w < 8; w++)
                s += s_red[w][tid];
            const int row = b * PQ + qc * QCHUNK + q;
            out[(size_t)row * PK + tid] = -sqrtf(s);
        }
        __syncthreads();   // protect s_red before next iteration
    }
}

// ---------------------------------------------------------------------------
// kernel_launch: inputs per metadata order:
//   [0] support_x f32 [32,50,128,64]
//   [1] support_y i32 [32,50]
//   [2] query_x   f32 [32,75,128,64]
//   [3] W         f32 [64,256]
//   [4] b         f32 [256]        (unused — cancels in distances)
// output: f32 [2400, 5]
// ---------------------------------------------------------------------------
extern "C" void kernel_launch(void* const* d_in, const int* in_sizes, int n_in,
                              void* d_out, int out_size)
{
    const float* support_x = (const float*)d_in[0];
    const int*   support_y = (const int*)  d_in[1];
    const float* query_x   = (const float*)d_in[2];
    const float* W         = (const float*)d_in[3];
    float*       out       = (float*)d_out;

    float* xm;  cudaGetSymbolAddress((void**)&xm,  g_xm);
    float* pxm; cudaGetSymbolAddress((void**)&pxm, g_pxm);

    meanpool_kernel<<<N_SAMPLES, 256>>>(support_x, query_x, xm);
    proto_kernel<<<PB, 64>>>(support_y, xm, pxm);
    logits_kernel<<<PB * (PQ / QCHUNK), 256>>>(xm, pxm, W, out);
}